// round 13
// baseline (speedup 1.0000x reference)
#include <cuda_runtime.h>
#include <cuda_fp16.h>
#include <cstdint>

// ============================================================================
// IWConLoss on GB300 (sm_103a via compute_103 baseline PTX):
//   scores = Q @ Neg^T / tau ; loss = mean( LSE_row(scores) - (Q.P)/tau )
// R12: balanced one-wave persistent grid (444 CTAs = 148 SMs x occ3), each CTA
// owns a contiguous ~37-tile slice of the global tile space. Removes the 23%
// wave-quantization tail that capped R6-R11 at ~99us main.
// fp16-accumulator HMMA (validated rel_err 3.2e-6), fused reduction.
// ============================================================================

static constexpr int NQ   = 8192;
static constexpr int NNEG = 16384;
static constexpr int KD   = 128;

static constexpr int MB = 128;        // query rows per row-block
static constexpr int NT = 64;         // negatives per tile
static constexpr int RB = NQ / MB;    // 64 row blocks
static constexpr int TPR = NNEG / NT; // 256 tiles per row-block
static constexpr int TOT = RB * TPR;  // 16384 total tile units (2^14)
static constexpr int NCTA = 444;      // 148 SMs x 3 CTAs = exactly one wave
static constexpr int MAXSLOT = 16;    // >= max CTAs covering one row-block (<=9)

static constexpr int PITCH = 272;                   // 128 fp16 + 8 pad
static constexpr int QT_BYTES = 128 * PITCH;        // 34816
static constexpr int NT_BYTES = NT * PITCH;         // 17408
static constexpr int SM_SCR = QT_BYTES + 2 * NT_BYTES;  // 69632
static constexpr int SMEM_TOTAL = SM_SCR + 4096;    // 73728 -> 3 CTAs/SM

static constexpr float INV_TAU = 5.0f;
static constexpr float C_T  = 7.2134752044448170f;  // log2(e)/tau
static constexpr float LN2F = 0.69314718055994531f;

// ---------------- device scratch ----------------
__device__ __align__(16) __half g_qh[NQ * KD];
__device__ __align__(16) __half g_nh[NNEG * KD];
__device__ float g_poslogit[NQ];
__device__ float g_pm[RB * MAXSLOT * 128];   // [rb][slot][row]; unwritten slots s=0
__device__ float g_ps[RB * MAXSLOT * 128];
__device__ double g_part[RB];
__device__ int g_rbctr[RB];                  // zero-init; reset by reducer
__device__ int g_ctr;                        // zero-init; reset by final

// ---------------- helpers ----------------
__device__ __forceinline__ uint32_t smem_u32(const void* p) {
    uint32_t a;
    asm("{ .reg .u64 t; cvta.to.shared.u64 t, %1; cvt.u32.u64 %0, t; }"
        : "=r"(a) : "l"(p));
    return a;
}
__device__ __forceinline__ float ex2f(float x) {
    float r; asm("ex2.approx.ftz.f32 %0, %1;" : "=f"(r) : "f"(x)); return r;
}
__device__ __forceinline__ void cpa16(uint32_t dst, const void* src) {
    asm volatile("cp.async.cg.shared.global [%0], [%1], 16;" :: "r"(dst), "l"(src));
}
#define CP_COMMIT() asm volatile("cp.async.commit_group;" ::: "memory")
#define CP_WAIT(n)  asm volatile("cp.async.wait_group %0;" :: "n"(n) : "memory")

__device__ __forceinline__ void ldsm4(uint32_t& r0, uint32_t& r1, uint32_t& r2,
                                      uint32_t& r3, uint32_t addr) {
    asm volatile("ldmatrix.sync.aligned.m8n8.x4.shared.b16 {%0,%1,%2,%3}, [%4];"
        : "=r"(r0), "=r"(r1), "=r"(r2), "=r"(r3) : "r"(addr));
}
// fp16-accumulator MMA: D,C packed half2 (2 regs per warp-tile)
__device__ __forceinline__ void mma16816_f16(uint32_t* d, const uint32_t* a,
                                             const uint32_t b0, const uint32_t b1) {
    asm volatile(
        "mma.sync.aligned.m16n8k16.row.col.f16.f16.f16.f16 "
        "{%0,%1}, {%2,%3,%4,%5}, {%6,%7}, {%0,%1};"
        : "+r"(d[0]), "+r"(d[1])
        : "r"(a[0]), "r"(a[1]), "r"(a[2]), "r"(a[3]), "r"(b0), "r"(b1));
}

// ============================================================================
// combined prep kernel
// ============================================================================
static constexpr int NB_NEG = (NNEG * KD) / 1024;   // 2048 blocks

__global__ void prep_kernel(const float* __restrict__ q, const float* __restrict__ pos,
                            const float* __restrict__ neg) {
    if (blockIdx.x < NB_NEG) {
        int i = (blockIdx.x * 256 + threadIdx.x) * 4;
        float4 v = *reinterpret_cast<const float4*>(neg + i);
        __half2* o = reinterpret_cast<__half2*>(g_nh + i);
        o[0] = __floats2half2_rn(v.x, v.y);
        o[1] = __floats2half2_rn(v.z, v.w);
    } else {
        int b = blockIdx.x - NB_NEG;
        int w = threadIdx.x >> 5, lane = threadIdx.x & 31;
        int row = b * 8 + w;
        const float4 q4 = *reinterpret_cast<const float4*>(q + row * KD + lane * 4);
        const float4 p4 = *reinterpret_cast<const float4*>(pos + row * KD + lane * 4);
        float d = q4.x * p4.x + q4.y * p4.y + q4.z * p4.z + q4.w * p4.w;
        #pragma unroll
        for (int o = 16; o > 0; o >>= 1) d += __shfl_xor_sync(0xffffffffu, d, o);
        if (lane == 0) g_poslogit[row] = d * INV_TAU;

        __half2* o = reinterpret_cast<__half2*>(g_qh + row * KD + lane * 4);
        o[0] = __floats2half2_rn(q4.x * C_T, q4.y * C_T);
        o[1] = __floats2half2_rn(q4.z * C_T, q4.w * C_T);
    }
}

// ============================================================================
// main fused kernel
// ============================================================================
__device__ __forceinline__ void copy_q_block(uint32_t sb, int tid, int qbase) {
    #pragma unroll
    for (int j = 0; j < 8; j++) {
        int idx = j * 256 + tid;
        int row = idx >> 4, c = idx & 15;
        cpa16(sb + (uint32_t)(row * PITCH + c * 16), g_qh + (qbase + row) * KD + c * 8);
    }
}
// neg tile for global tile index g lives at rows (g & 255) * 64
__device__ __forceinline__ void copy_neg_tile(uint32_t sb, int tid, int stage, int g) {
    uint32_t base = sb + (uint32_t)(QT_BYTES + NT_BYTES * stage);
    const int rowbase = (g & (TPR - 1)) * NT;
    #pragma unroll
    for (int j = 0; j < 4; j++) {
        int idx = j * 256 + tid;
        int row = idx >> 4, c = idx & 15;
        cpa16(base + (uint32_t)(row * PITCH + c * 16),
              g_nh + (rowbase + row) * KD + c * 8);
    }
}

// online LSE over one 32x32 warp tile; C packed half2 [mi][ni][rowhalf]
__device__ __forceinline__ void epilogue(const uint32_t C[2][4][2], float* mrun, float* srun) {
    #pragma unroll
    for (int j = 0; j < 4; j++) {
        const int mi = j >> 1, hi = j & 1;
        float2 f0 = __half22float2(*reinterpret_cast<const __half2*>(&C[mi][0][hi]));
        float2 f1 = __half22float2(*reinterpret_cast<const __half2*>(&C[mi][1][hi]));
        float2 f2 = __half22float2(*reinterpret_cast<const __half2*>(&C[mi][2][hi]));
        float2 f3 = __half22float2(*reinterpret_cast<const __half2*>(&C[mi][3][hi]));
        float x0 = f0.x, x1 = f0.y, x2 = f1.x, x3 = f1.y;
        float x4 = f2.x, x5 = f2.y, x6 = f3.x, x7 = f3.y;
        float tmax = fmaxf(fmaxf(fmaxf(x0, x1), fmaxf(x2, x3)),
                           fmaxf(fmaxf(x4, x5), fmaxf(x6, x7)));
        if (tmax > mrun[j]) {
            srun[j] *= ex2f(mrun[j] - tmax);
            mrun[j] = tmax;
        }
        const float mn = mrun[j];
        srun[j] += ex2f(x0 - mn) + ex2f(x1 - mn) + ex2f(x2 - mn) + ex2f(x3 - mn)
                 + ex2f(x4 - mn) + ex2f(x5 - mn) + ex2f(x6 - mn) + ex2f(x7 - mn);
    }
}

__global__ __launch_bounds__(256, 3) void conloss_main_kernel(float* __restrict__ out) {
    extern __shared__ char smem[];
    uint32_t sb = smem_u32(smem);
    float*  smm = reinterpret_cast<float*>(smem + SM_SCR);          // [2][128]
    float*  sms = smm + 256;
    double* shd = reinterpret_cast<double*>(smem + SM_SCR + 2048);  // [256]
    __shared__ int lastArr;

    const int tid = threadIdx.x, warp = tid >> 5, lane = tid & 31;
    const int wm = warp & 3;          // 4 warp-rows of 32
    const int wn = warp >> 2;         // 2 warp-cols of 32
    const int c = blockIdx.x;

    // contiguous slice of the global tile space: c(g) = (g*NCTA)>>14
    const int gStart = (c * TOT + NCTA - 1) / NCTA;
    const int gEnd   = ((c + 1) * TOT + NCTA - 1) / NCTA;
    const int nT = gEnd - gStart;     // 36 or 37
    int rbCur = gStart >> 8;

    copy_q_block(sb, tid, rbCur * MB);
    copy_neg_tile(sb, tid, 0, gStart);
    CP_COMMIT();
    copy_neg_tile(sb, tid, 1, gStart + 1);
    CP_COMMIT();

    const uint32_t aBase = sb + (uint32_t)((wm * 32 + (lane & 15)) * PITCH + ((lane >> 4) * 16));
    const uint32_t bOff = (uint32_t)(((wn * 32) + (lane & 7) + ((lane >> 4) << 3)) * PITCH
                                     + (((lane >> 3) & 1) * 16));

    uint32_t C[2][4][2];
    float mrun[4], srun[4];
    #pragma unroll
    for (int j = 0; j < 4; j++) { mrun[j] = -1e30f; srun[j] = 0.0f; }

    #pragma unroll 1
    for (int k = 0; k < nT; k++) {
        const int g = gStart + k;
        CP_WAIT(1);
        __syncthreads();

        #pragma unroll
        for (int mi = 0; mi < 2; mi++)
            #pragma unroll
            for (int ni = 0; ni < 4; ni++) { C[mi][ni][0] = 0u; C[mi][ni][1] = 0u; }

        const uint32_t bBase = sb + (uint32_t)(QT_BYTES + NT_BYTES * (k & 1)) + bOff;

        #pragma unroll
        for (int ks = 0; ks < 8; ks++) {
            uint32_t A[2][4], B[2][4];
            #pragma unroll
            for (int mi = 0; mi < 2; mi++)
                ldsm4(A[mi][0], A[mi][1], A[mi][2], A[mi][3],
                      aBase + (uint32_t)(mi * 16 * PITCH + ks * 32));
            #pragma unroll
            for (int np = 0; np < 2; np++)
                ldsm4(B[np][0], B[np][1], B[np][2], B[np][3],
                      bBase + (uint32_t)(np * 16 * PITCH + ks * 32));
            #pragma unroll
            for (int mi = 0; mi < 2; mi++)
                #pragma unroll
                for (int ni = 0; ni < 4; ni++)
                    mma16816_f16(C[mi][ni], A[mi],
                                 B[ni >> 1][(ni & 1) * 2], B[ni >> 1][(ni & 1) * 2 + 1]);
        }
        __syncthreads();

        if (k + 2 < nT) copy_neg_tile(sb, tid, k & 1, g + 2);
        CP_COMMIT();

        epilogue(C, mrun, srun);

        // ---------------- segment boundary / end: flush partial ----------------
        const bool last = (k == nT - 1);
        if (last || ((g + 1) >> 8) != rbCur) {
            // combine the 4 lanes sharing each row
            #pragma unroll
            for (int j = 0; j < 4; j++) {
                #pragma unroll
                for (int off = 1; off <= 2; off <<= 1) {
                    float mo = __shfl_xor_sync(0xffffffffu, mrun[j], off);
                    float so = __shfl_xor_sync(0xffffffffu, srun[j], off);
                    float M = fmaxf(mrun[j], mo);
                    srun[j] = srun[j] * ex2f(mrun[j] - M) + so * ex2f(mo - M);
                    mrun[j] = M;
                }
            }
            __syncthreads();   // scratch region free from prior use
            if ((lane & 3) == 0) {
                #pragma unroll
                for (int j = 0; j < 4; j++) {
                    int row = wm * 32 + (j >> 1) * 16 + (j & 1) * 8 + (lane >> 2);
                    smm[wn * 128 + row] = mrun[j];
                    sms[wn * 128 + row] = srun[j];
                }
            }
            __syncthreads();
            const int cFirst = (rbCur * TPR * NCTA) >> 14;
            if (tid < 128) {
                float m0 = smm[tid], m1 = smm[128 + tid];
                float M = fmaxf(m0, m1);
                float S = sms[tid] * ex2f(m0 - M) + sms[128 + tid] * ex2f(m1 - M);
                int slot = c - cFirst;
                g_pm[(rbCur * MAXSLOT + slot) * 128 + tid] = M;
                g_ps[(rbCur * MAXSLOT + slot) * 128 + tid] = S;
            }
            __syncthreads();
            __threadfence();
            if (tid == 0) {
                int cLast = ((rbCur * TPR + TPR - 1) * NCTA) >> 14;
                int nCover = cLast - cFirst + 1;
                lastArr = (atomicAdd(&g_rbctr[rbCur], 1) == nCover - 1);
            }
            __syncthreads();
            if (lastArr) {
                __threadfence();
                double part = 0.0;
                if (tid < 128) {
                    int cLast = ((rbCur * TPR + TPR - 1) * NCTA) >> 14;
                    int nCover = cLast - cFirst + 1;
                    const float* pm = g_pm + rbCur * MAXSLOT * 128 + tid;
                    const float* ps = g_ps + rbCur * MAXSLOT * 128 + tid;
                    float M = -1e30f;
                    for (int j = 0; j < nCover; j++) {
                        float sj = ps[j * 128];
                        float mj = pm[j * 128];
                        if (sj > 0.0f) M = fmaxf(M, mj);
                    }
                    float S = 0.0f;
                    for (int j = 0; j < nCover; j++)
                        S += ps[j * 128] * ex2f(pm[j * 128] - M);
                    float lse = LN2F * (M + log2f(S));
                    part = (double)(lse - g_poslogit[rbCur * MB + tid]);
                }
                shd[tid] = part;
                __syncthreads();
                for (int o = 128; o > 0; o >>= 1) {
                    if (tid < o) shd[tid] += shd[tid + o];
                    __syncthreads();
                }
                if (tid == 0) {
                    g_part[rbCur] = shd[0];
                    g_rbctr[rbCur] = 0;                 // reset for next replay
                    __threadfence();
                    if (atomicAdd(&g_ctr, 1) == RB - 1) {
                        __threadfence();
                        double acc = 0.0;
                        #pragma unroll
                        for (int i = 0; i < RB; i++) acc += g_part[i];
                        out[0] = (float)(acc / (double)NQ);
                        g_ctr = 0;                      // reset for next replay
                    }
                }
                __syncthreads();   // protect shd before any later reuse
            }
            // ---------------- start next segment ----------------
            if (!last) {
                rbCur = (g + 1) >> 8;
                #pragma unroll
                for (int j = 0; j < 4; j++) { mrun[j] = -1e30f; srun[j] = 0.0f; }
                copy_q_block(sb, tid, rbCur * MB);
                CP_COMMIT();
                CP_WAIT(0);        // drain Q + outstanding neg prefetches
                __syncthreads();
            }
        }
    }
}

// ============================================================================
// kernel_launch
// ============================================================================
extern "C" void kernel_launch(void* const* d_in, const int* in_sizes, int n_in,
                              void* d_out, int out_size) {
    (void)n_in; (void)out_size;
    const float* a0 = (const float*)d_in[0];
    const float* a1 = (const float*)d_in[1];
    const float* a2 = (const float*)d_in[2];
    const float *q, *p, *neg;
    if (in_sizes[2] == NNEG * KD)      { q = a0; p = a1; neg = a2; }
    else if (in_sizes[1] == NNEG * KD) { q = a0; p = a2; neg = a1; }
    else                               { q = a1; p = a2; neg = a0; }

    cudaFuncSetAttribute(conloss_main_kernel,
                         cudaFuncAttributeMaxDynamicSharedMemorySize, SMEM_TOTAL);

    prep_kernel<<<NB_NEG + NQ / 8, 256>>>(q, p, neg);
    conloss_main_kernel<<<NCTA, 256, SMEM_TOTAL>>>((float*)d_out);
}

// round 14
// speedup vs baseline: 1.0371x; 1.0371x over previous
#include <cuda_runtime.h>
#include <cuda_fp16.h>
#include <cstdint>

// ============================================================================
// IWConLoss on GB300 (sm_103a via compute_103 baseline PTX):
//   scores = Q @ Neg^T / tau ; loss = mean( LSE_row(scores) - (Q.P)/tau )
// R13: 4-warp CTAs, 32x64 warp tiles, FULL A-register hoist (reg cap 170 at
// occ3 with 128-thread CTAs). Crossbar per tile drops 145KB -> 81KB (below the
// tensor floor). Each SMSP hosts 3 unsynchronized warps from 3 CTAs.
// fp16 accumulators; fused counter reduction; 64x16 multi-wave dispatch.
// ============================================================================

static constexpr int NQ   = 8192;
static constexpr int NNEG = 16384;
static constexpr int KD   = 128;

static constexpr int MB = 128;      // query rows per CTA
static constexpr int NT = 64;       // negatives per tile
static constexpr int SPLITS = 16;   // grid = 64 x 16 = 1024 CTAs
static constexpr int RB = NQ / MB;  // 64 row blocks
static constexpr int TILES = NNEG / SPLITS / NT;   // 16
static constexpr int STAGES = 2;

static constexpr int PITCH = 272;                   // 128 fp16 + 8 pad
static constexpr int QT_BYTES = 128 * PITCH;        // 34816
static constexpr int NT_BYTES = NT * PITCH;         // 17408
static constexpr int SMEM_TOTAL = QT_BYTES + STAGES * NT_BYTES;  // 69632 -> occ3

static constexpr float INV_TAU = 5.0f;
static constexpr float C_T  = 7.2134752044448170f;  // log2(e)/tau
static constexpr float LN2F = 0.69314718055994531f;

// ---------------- device scratch ----------------
__device__ __align__(16) __half g_qh[NQ * KD];
__device__ __align__(16) __half g_nh[NNEG * KD];
__device__ float g_poslogit[NQ];
__device__ float g_pm[SPLITS * NQ];     // [split][row]
__device__ float g_ps[SPLITS * NQ];
__device__ double g_part[RB];
__device__ int g_rbctr[RB];             // zero-init; reset after use
__device__ int g_ctr;                   // zero-init; reset after use

// ---------------- helpers ----------------
__device__ __forceinline__ uint32_t smem_u32(const void* p) {
    uint32_t a;
    asm("{ .reg .u64 t; cvta.to.shared.u64 t, %1; cvt.u32.u64 %0, t; }"
        : "=r"(a) : "l"(p));
    return a;
}
__device__ __forceinline__ float ex2f(float x) {
    float r; asm("ex2.approx.ftz.f32 %0, %1;" : "=f"(r) : "f"(x)); return r;
}
__device__ __forceinline__ void cpa16(uint32_t dst, const void* src) {
    asm volatile("cp.async.cg.shared.global [%0], [%1], 16;" :: "r"(dst), "l"(src));
}
#define CP_COMMIT() asm volatile("cp.async.commit_group;" ::: "memory")
#define CP_WAIT(n)  asm volatile("cp.async.wait_group %0;" :: "n"(n) : "memory")

__device__ __forceinline__ void ldsm4(uint32_t& r0, uint32_t& r1, uint32_t& r2,
                                      uint32_t& r3, uint32_t addr) {
    asm volatile("ldmatrix.sync.aligned.m8n8.x4.shared.b16 {%0,%1,%2,%3}, [%4];"
        : "=r"(r0), "=r"(r1), "=r"(r2), "=r"(r3) : "r"(addr));
}
// fp16-accumulator MMA: D,C packed half2
__device__ __forceinline__ void mma16816_f16(uint32_t* d, const uint32_t* a,
                                             const uint32_t b0, const uint32_t b1) {
    asm volatile(
        "mma.sync.aligned.m16n8k16.row.col.f16.f16.f16.f16 "
        "{%0,%1}, {%2,%3,%4,%5}, {%6,%7}, {%0,%1};"
        : "+r"(d[0]), "+r"(d[1])
        : "r"(a[0]), "r"(a[1]), "r"(a[2]), "r"(a[3]), "r"(b0), "r"(b1));
}

// ============================================================================
// combined prep kernel
// ============================================================================
static constexpr int NB_NEG = (NNEG * KD) / 1024;   // 2048 blocks

__global__ void prep_kernel(const float* __restrict__ q, const float* __restrict__ pos,
                            const float* __restrict__ neg) {
    if (blockIdx.x < NB_NEG) {
        int i = (blockIdx.x * 256 + threadIdx.x) * 4;
        float4 v = *reinterpret_cast<const float4*>(neg + i);
        __half2* o = reinterpret_cast<__half2*>(g_nh + i);
        o[0] = __floats2half2_rn(v.x, v.y);
        o[1] = __floats2half2_rn(v.z, v.w);
    } else {
        int b = blockIdx.x - NB_NEG;
        int w = threadIdx.x >> 5, lane = threadIdx.x & 31;
        int row = b * 8 + w;
        const float4 q4 = *reinterpret_cast<const float4*>(q + row * KD + lane * 4);
        const float4 p4 = *reinterpret_cast<const float4*>(pos + row * KD + lane * 4);
        float d = q4.x * p4.x + q4.y * p4.y + q4.z * p4.z + q4.w * p4.w;
        #pragma unroll
        for (int o = 16; o > 0; o >>= 1) d += __shfl_xor_sync(0xffffffffu, d, o);
        if (lane == 0) g_poslogit[row] = d * INV_TAU;

        __half2* o = reinterpret_cast<__half2*>(g_qh + row * KD + lane * 4);
        o[0] = __floats2half2_rn(q4.x * C_T, q4.y * C_T);
        o[1] = __floats2half2_rn(q4.z * C_T, q4.w * C_T);
    }
}

// ============================================================================
// main fused kernel: 128 threads (4 warps), warp tile 32x64
// ============================================================================
__device__ __forceinline__ void copy_q_block(uint32_t sb, int tid, int qbase) {
    #pragma unroll
    for (int j = 0; j < 16; j++) {
        int idx = j * 128 + tid;             // 0..2047 (128 rows x 16 chunks)
        int row = idx >> 4, c = idx & 15;
        cpa16(sb + (uint32_t)(row * PITCH + c * 16), g_qh + (qbase + row) * KD + c * 8);
    }
}
__device__ __forceinline__ void copy_neg_tile(uint32_t sb, int tid, int stage, int rowbase) {
    uint32_t base = sb + (uint32_t)(QT_BYTES + NT_BYTES * stage);
    #pragma unroll
    for (int j = 0; j < 8; j++) {
        int idx = j * 128 + tid;             // 0..1023 (64 rows x 16 chunks)
        int row = idx >> 4, c = idx & 15;
        cpa16(base + (uint32_t)(row * PITCH + c * 16),
              g_nh + (rowbase + row) * KD + c * 8);
    }
}

// online LSE over one 32x64 warp tile; C packed half2 [mi][ni][rowhalf]
__device__ __forceinline__ void epilogue(const uint32_t C[2][8][2], float* mrun, float* srun) {
    #pragma unroll
    for (int j = 0; j < 4; j++) {
        const int mi = j >> 1, hi = j & 1;
        float x[16];
        #pragma unroll
        for (int ni = 0; ni < 8; ni++) {
            float2 f = __half22float2(*reinterpret_cast<const __half2*>(&C[mi][ni][hi]));
            x[ni * 2]     = f.x;
            x[ni * 2 + 1] = f.y;
        }
        float tmax = x[0];
        #pragma unroll
        for (int i = 1; i < 16; i++) tmax = fmaxf(tmax, x[i]);
        if (tmax > mrun[j]) {
            srun[j] *= ex2f(mrun[j] - tmax);
            mrun[j] = tmax;
        }
        const float mn = mrun[j];
        float acc = 0.0f;
        #pragma unroll
        for (int i = 0; i < 16; i++) acc += ex2f(x[i] - mn);
        srun[j] += acc;
    }
}

__global__ __launch_bounds__(128, 3) void conloss_main_kernel(float* __restrict__ out) {
    extern __shared__ char smem[];
    uint32_t sb = smem_u32(smem);
    const int tid = threadIdx.x, warp = tid >> 5, lane = tid & 31;
    const int rb = blockIdx.x;
    const int qbase = rb * MB;
    const int negbase = blockIdx.y * (NNEG / SPLITS);

    copy_q_block(sb, tid, qbase);
    copy_neg_tile(sb, tid, 0, negbase);
    CP_COMMIT();                                  // group: Q + tile0
    copy_neg_tile(sb, tid, 1, negbase + NT);
    CP_COMMIT();                                  // group: tile1

    // ---- hoist the ENTIRE A (Q) tile into registers (once per CTA) ----
    CP_WAIT(1);                                   // Q + tile0 resident
    __syncthreads();
    const uint32_t aBase = sb + (uint32_t)((warp * 32 + (lane & 15)) * PITCH
                                           + ((lane >> 4) * 16));
    uint32_t A[2][8][4];
    #pragma unroll
    for (int mi = 0; mi < 2; mi++)
        #pragma unroll
        for (int ks = 0; ks < 8; ks++)
            ldsm4(A[mi][ks][0], A[mi][ks][1], A[mi][ks][2], A[mi][ks][3],
                  aBase + (uint32_t)(mi * 16 * PITCH + ks * 32));

    // B: each warp reads ALL 64 cols; 4 ldsm.x4 per ks (16-col blocks)
    const uint32_t bOff = (uint32_t)(((lane & 7) + ((lane >> 4) << 3)) * PITCH
                                     + (((lane >> 3) & 1) * 16));

    uint32_t C[2][8][2];
    float mrun[4], srun[4];
    #pragma unroll
    for (int j = 0; j < 4; j++) { mrun[j] = -1e30f; srun[j] = 0.0f; }

    #pragma unroll 1
    for (int t = 0; t < TILES; t++) {
        CP_WAIT(STAGES - 1);
        __syncthreads();

        #pragma unroll
        for (int mi = 0; mi < 2; mi++)
            #pragma unroll
            for (int ni = 0; ni < 8; ni++) { C[mi][ni][0] = 0u; C[mi][ni][1] = 0u; }

        const uint32_t bBase = sb + (uint32_t)(QT_BYTES + NT_BYTES * (t & 1)) + bOff;

        #pragma unroll
        for (int ks = 0; ks < 8; ks++) {
            uint32_t B[4][4];                     // 4 col-blocks x 4 regs
            #pragma unroll
            for (int cb = 0; cb < 4; cb++)
                ldsm4(B[cb][0], B[cb][1], B[cb][2], B[cb][3],
                      bBase + (uint32_t)(cb * 16 * PITCH + ks * 32));
            #pragma unroll
            for (int mi = 0; mi < 2; mi++)
                #pragma unroll
                for (int ni = 0; ni < 8; ni++)
                    mma16816_f16(C[mi][ni], A[mi][ks],
                                 B[ni >> 1][(ni & 1) * 2], B[ni >> 1][(ni & 1) * 2 + 1]);
        }
        __syncthreads();

        if (t + STAGES < TILES)
            copy_neg_tile(sb, tid, t & 1, negbase + (t + STAGES) * NT);
        CP_COMMIT();

        epilogue(C, mrun, srun);
    }

    // combine the 4 lanes sharing each row (row fully owned by this warp)
    #pragma unroll
    for (int j = 0; j < 4; j++) {
        #pragma unroll
        for (int off = 1; off <= 2; off <<= 1) {
            float mo = __shfl_xor_sync(0xffffffffu, mrun[j], off);
            float so = __shfl_xor_sync(0xffffffffu, srun[j], off);
            float M = fmaxf(mrun[j], mo);
            srun[j] = srun[j] * ex2f(mrun[j] - M) + so * ex2f(mo - M);
            mrun[j] = M;
        }
    }
    // direct per-row partial write: no cross-warp combine needed
    if ((lane & 3) == 0) {
        #pragma unroll
        for (int j = 0; j < 4; j++) {
            int row = warp * 32 + (j >> 1) * 16 + (j & 1) * 8 + (lane >> 2);
            g_pm[blockIdx.y * NQ + qbase + row] = mrun[j];
            g_ps[blockIdx.y * NQ + qbase + row] = srun[j];
        }
    }

    // ---------------- fused reduction ----------------
    __threadfence();
    __syncthreads();
    __shared__ int lastRb;
    if (tid == 0)
        lastRb = (atomicAdd(&g_rbctr[rb], 1) == SPLITS - 1);
    __syncthreads();
    if (!lastRb) return;

    __threadfence();
    double part = 0.0;
    {
        int r = qbase + tid;
        float m[SPLITS], s[SPLITS];
        #pragma unroll
        for (int j = 0; j < SPLITS; j++) {
            m[j] = g_pm[j * NQ + r];
            s[j] = g_ps[j * NQ + r];
        }
        float M = m[0];
        #pragma unroll
        for (int j = 1; j < SPLITS; j++) M = fmaxf(M, m[j]);
        float S = 0.0f;
        #pragma unroll
        for (int j = 0; j < SPLITS; j++) S += s[j] * ex2f(m[j] - M);
        float lse = LN2F * (M + log2f(S));
        part = (double)(lse - g_poslogit[r]);
    }
    double* shd = reinterpret_cast<double*>(smem);   // tiles no longer needed
    shd[tid] = part;
    __syncthreads();
    for (int o = 64; o > 0; o >>= 1) {
        if (tid < o) shd[tid] += shd[tid + o];
        __syncthreads();
    }
    if (tid == 0) {
        g_part[rb] = shd[0];
        g_rbctr[rb] = 0;                 // reset for next graph replay
        __threadfence();
        if (atomicAdd(&g_ctr, 1) == RB - 1) {
            __threadfence();
            double acc = 0.0;
            #pragma unroll
            for (int i = 0; i < RB; i++) acc += g_part[i];
            out[0] = (float)(acc / (double)NQ);
            g_ctr = 0;                   // reset for next graph replay
        }
    }
}

// ============================================================================
// kernel_launch
// ============================================================================
extern "C" void kernel_launch(void* const* d_in, const int* in_sizes, int n_in,
                              void* d_out, int out_size) {
    (void)n_in; (void)out_size;
    const float* a0 = (const float*)d_in[0];
    const float* a1 = (const float*)d_in[1];
    const float* a2 = (const float*)d_in[2];
    const float *q, *p, *neg;
    if (in_sizes[2] == NNEG * KD)      { q = a0; p = a1; neg = a2; }
    else if (in_sizes[1] == NNEG * KD) { q = a0; p = a2; neg = a1; }
    else                               { q = a1; p = a2; neg = a0; }

    cudaFuncSetAttribute(conloss_main_kernel,
                         cudaFuncAttributeMaxDynamicSharedMemorySize, SMEM_TOTAL);

    prep_kernel<<<NB_NEG + NQ / 8, 256>>>(q, p, neg);
    conloss_main_kernel<<<dim3(RB, SPLITS), 128, SMEM_TOTAL>>>((float*)d_out);
}